// round 11
// baseline (speedup 1.0000x reference)
#include <cuda_runtime.h>
#include <math.h>

#define D_FEAT 8192
#define T_RES  2048
#define ORDER  16
#define DTAU   0.08
#define REG    0.0001f
#define EPS_C  1e-15f

#define ROW_BLOCKS 512   // k_A: 4 rows/block, 2 warps per row
#define COL_BLOCKS 256   // prologue col: 32 cols/block, 512 threads
#define UB1       512    // k_B1 blocks: 2 t-halves x 256 col-blocks
#define NW  256
#define NWC 512

// ---------------- device scratch (no allocations allowed) ----------------
__device__ float g_s[ORDER * T_RES];          // s_j = R q_j
__device__ float g_sf[T_RES];                 // R f
__device__ float g_Q[ORDER * D_FEAT];         // Lanczos basis
__device__ float g_wf[D_FEAT];                // current unnormalized basis vector
__device__ float g_upart[2 * D_FEAT];         // t-half partials of u = R^T s_j
__device__ float g_nrm2_part[COL_BLOCKS];     // ||wf||^2 partials
__device__ float g_cpart[ROW_BLOCKS * ORDER]; // per-row-block partials of c_k
__device__ float g_b[ORDER + 1];              // g_b[0]=||F||, g_b[j]=beta[j-1]
__device__ float g_alpha[ORDER];

__device__ __forceinline__ void fma4(float4& a, const float4 r, const float4 v) {
    a.x = fmaf(r.x, v.x, a.x); a.y = fmaf(r.y, v.y, a.y);
    a.z = fmaf(r.z, v.z, a.z); a.w = fmaf(r.w, v.w, a.w);
}
__device__ __forceinline__ void fmas(float4& a, const float4 r, const float s) {
    a.x = fmaf(r.x, s, a.x); a.y = fmaf(r.y, s, a.y);
    a.z = fmaf(r.z, s, a.z); a.w = fmaf(r.w, s, a.w);
}

// ================= prologue row: sf = R f (warp per row) =================
__global__ void k_row_f(const float* __restrict__ R, const float* __restrict__ f) {
    int tx = threadIdx.x, lane = tx & 31, w = tx >> 5;
    int r = blockIdx.x * 8 + w;
    const float4* R4 = (const float4*)(R + (size_t)r * D_FEAT);
    const float4* f4 = (const float4*)f;
    float4 aA = make_float4(0.f,0.f,0.f,0.f), aB = aA;
    #pragma unroll 8
    for (int it = 0; it < 64; it += 2) {
        int i0 = it * 32 + lane, i1 = i0 + 32;
        fma4(aA, R4[i0], f4[i0]);
        fma4(aB, R4[i1], f4[i1]);
    }
    float acc = (aA.x + aA.y) + (aA.z + aA.w) + (aB.x + aB.y) + (aB.z + aB.w);
    #pragma unroll
    for (int o = 16; o; o >>= 1) acc += __shfl_xor_sync(0xffffffffu, acc, o);
    if (lane == 0) g_sf[r] = acc;
}

// ====== prologue col: F = R^T sf + E f ; wf = F ; ||F||^2 partials ======
__global__ void k_prologue_col(const float* __restrict__ R, const float* __restrict__ f) {
    __shared__ float s_sm[T_RES];
    __shared__ float4 sh[NWC];
    __shared__ float sh_r1[16], sh_r2[16];
    __shared__ float shE;
    int tx = threadIdx.x, lane = tx & 31, w = tx >> 5;
    const float4* f4 = (const float4*)f;

    float ssf = 0.f;
    for (int i = tx; i < T_RES / 4; i += NWC) {
        float4 v = ((const float4*)g_sf)[i];
        ((float4*)s_sm)[i] = v;
        ssf = fmaf(v.x, v.x, fmaf(v.y, v.y, fmaf(v.z, v.z, fmaf(v.w, v.w, ssf))));
    }
    float ff = 0.f;
    for (int i = tx; i < D_FEAT / 4; i += NWC) {
        float4 v = f4[i];
        ff = fmaf(v.x, v.x, fmaf(v.y, v.y, fmaf(v.z, v.z, fmaf(v.w, v.w, ff))));
    }
    #pragma unroll
    for (int o = 16; o; o >>= 1) {
        ssf += __shfl_xor_sync(0xffffffffu, ssf, o);
        ff  += __shfl_xor_sync(0xffffffffu, ff, o);
    }
    if (lane == 0) { sh_r1[w] = ssf; sh_r2[w] = ff; }
    __syncthreads();
    if (tx == 0) {
        float a = 0.f, b = 0.f;
        #pragma unroll
        for (int i = 0; i < 16; i++) { a += sh_r1[i]; b += sh_r2[i]; }
        shE = -a / (b + EPS_C);
    }
    __syncthreads();

    int g = tx & 7, s = tx >> 3;          // s in [0,64)
    const float4* R4 = (const float4*)R;
    size_t cbase = (size_t)blockIdx.x * 8 + g;
    float4 a0 = make_float4(0.f,0.f,0.f,0.f), a1 = a0, a2 = a0, a3 = a0;
    #pragma unroll
    for (int it = 0; it < 32; it += 4) {
        int t0 = (it+0)*64 + s, t1 = (it+1)*64 + s, t2 = (it+2)*64 + s, t3 = (it+3)*64 + s;
        fmas(a0, R4[(size_t)t0 * (D_FEAT/4) + cbase], s_sm[t0]);
        fmas(a1, R4[(size_t)t1 * (D_FEAT/4) + cbase], s_sm[t1]);
        fmas(a2, R4[(size_t)t2 * (D_FEAT/4) + cbase], s_sm[t2]);
        fmas(a3, R4[(size_t)t3 * (D_FEAT/4) + cbase], s_sm[t3]);
    }
    a0.x += a1.x; a0.y += a1.y; a0.z += a1.z; a0.w += a1.w;
    a2.x += a3.x; a2.y += a3.y; a2.z += a3.z; a2.w += a3.w;
    a0.x += a2.x; a0.y += a2.y; a0.z += a2.z; a0.w += a2.w;
    sh[tx] = a0;
    #pragma unroll
    for (int off = 256; off >= 8; off >>= 1) {
        __syncthreads();
        if (tx < off) {
            float4 a = sh[tx], b2 = sh[tx + off];
            a.x += b2.x; a.y += b2.y; a.z += b2.z; a.w += b2.w;
            sh[tx] = a;
        }
    }
    __syncthreads();

    if (tx < 32) {
        float u = ((const float*)sh)[tx];
        int col = blockIdx.x * 32 + tx;
        float F = fmaf(shE, f[col], u);
        g_wf[col] = F;
        float nrm = F * F;
        #pragma unroll
        for (int o = 16; o; o >>= 1) nrm += __shfl_xor_sync(0xffffffffu, nrm, o);
        if (tx == 0) g_nrm2_part[blockIdx.x] = nrm;
    }
}

// == k_A: b=||wf||; s_j = R*(wf/b); c-partials (4 rows/block, 2 warps/row) ==
__global__ void k_A(const float* __restrict__ R, int j, int npart) {
    __shared__ float sh_r[8];
    __shared__ float sh_invb;
    __shared__ float shp[8];
    int tx = threadIdx.x, lane = tx & 31, w = tx >> 5;

    float p = (tx < npart) ? g_nrm2_part[tx] : 0.f;
    #pragma unroll
    for (int o = 16; o; o >>= 1) p += __shfl_xor_sync(0xffffffffu, p, o);
    if (lane == 0) sh_r[w] = p;
    __syncthreads();
    if (tx == 0) {
        float n = 0.f;
        #pragma unroll
        for (int i = 0; i < 8; i++) n += sh_r[i];
        float b = sqrtf(n);
        if (blockIdx.x == 0) g_b[j] = b;
        sh_invb = 1.0f / fmaxf(b, 1e-30f);
    }
    __syncthreads();

    int r0 = blockIdx.x * 4;
    int row = r0 + (w >> 1), half = w & 1;
    const float4* R4 = (const float4*)(R + (size_t)row * D_FEAT) + half * 1024;
    const float4* w4 = (const float4*)g_wf + half * 1024;
    float4 aA = make_float4(0.f,0.f,0.f,0.f), aB = aA;
    #pragma unroll 8
    for (int it = 0; it < 32; it += 2) {
        int i0 = it * 32 + lane, i1 = i0 + 32;
        fma4(aA, R4[i0], w4[i0]);
        fma4(aB, R4[i1], w4[i1]);
    }
    float acc = (aA.x + aA.y) + (aA.z + aA.w) + (aB.x + aB.y) + (aB.z + aB.w);
    #pragma unroll
    for (int o = 16; o; o >>= 1) acc += __shfl_xor_sync(0xffffffffu, acc, o);
    if (lane == 0) shp[w] = acc;
    __syncthreads();

    if (w == 0) {
        float d = (lane < 8) ? shp[lane] : 0.f;
        d += __shfl_xor_sync(0xffffffffu, d, 1);   // lanes 0,2,4,6: full row dots
        float invb = sh_invb;
        float s0 = __shfl_sync(0xffffffffu, d, 0) * invb;
        float s1 = __shfl_sync(0xffffffffu, d, 2) * invb;
        float s2 = __shfl_sync(0xffffffffu, d, 4) * invb;
        float s3 = __shfl_sync(0xffffffffu, d, 6) * invb;
        if (lane < 4) {
            float sv = (lane == 0) ? s0 : (lane == 1) ? s1 : (lane == 2) ? s2 : s3;
            g_s[j * T_RES + r0 + lane] = sv;
        }
        if (lane < 16) {
            float cp = 0.f;
            if (lane <= j) {
                if (lane == j) {
                    cp = s0 * s0 + s1 * s1 + s2 * s2 + s3 * s3;
                } else {
                    const float* sk = g_s + (size_t)lane * T_RES + r0;
                    cp = sk[0] * s0 + sk[1] * s1 + sk[2] * s2 + sk[3] * s3;
                }
            }
            g_cpart[blockIdx.x * 16 + lane] = cp;
        }
    }
}

// ===== k_B1: u-half partials: g_upart[th][col] = sum_{t in half} R[t][col]*s_j[t] =====
__global__ void k_B1(const float* __restrict__ R, int j) {
    __shared__ float s_sm[1024];
    __shared__ float4 sh[NWC];
    int tx = threadIdx.x;
    int th = blockIdx.x >> 8;       // t-half
    int cb = blockIdx.x & 255;      // column block

    const float4* sj4 = (const float4*)(g_s + (size_t)j * T_RES + th * 1024);
    for (int i = tx; i < 256; i += NWC) ((float4*)s_sm)[i] = sj4[i];
    __syncthreads();

    int g = tx & 7, s = tx >> 3;    // s in [0,64)
    const float4* R4 = (const float4*)R + (size_t)th * 1024 * (D_FEAT / 4);
    size_t cbase = (size_t)cb * 8 + g;
    float4 a0 = make_float4(0.f,0.f,0.f,0.f), a1 = a0, a2 = a0, a3 = a0;
    #pragma unroll
    for (int it = 0; it < 16; it += 4) {
        int t0 = (it+0)*64 + s, t1 = (it+1)*64 + s, t2 = (it+2)*64 + s, t3 = (it+3)*64 + s;
        fmas(a0, R4[(size_t)t0 * (D_FEAT/4) + cbase], s_sm[t0]);
        fmas(a1, R4[(size_t)t1 * (D_FEAT/4) + cbase], s_sm[t1]);
        fmas(a2, R4[(size_t)t2 * (D_FEAT/4) + cbase], s_sm[t2]);
        fmas(a3, R4[(size_t)t3 * (D_FEAT/4) + cbase], s_sm[t3]);
    }
    a0.x += a1.x; a0.y += a1.y; a0.z += a1.z; a0.w += a1.w;
    a2.x += a3.x; a2.y += a3.y; a2.z += a3.z; a2.w += a3.w;
    a0.x += a2.x; a0.y += a2.y; a0.z += a2.z; a0.w += a2.w;
    sh[tx] = a0;
    #pragma unroll
    for (int off = 256; off >= 8; off >>= 1) {
        __syncthreads();
        if (tx < off) {
            float4 a = sh[tx], b2 = sh[tx + off];
            a.x += b2.x; a.y += b2.y; a.z += b2.z; a.w += b2.w;
            sh[tx] = a;
        }
    }
    __syncthreads();
    if (tx < 32) g_upart[th * D_FEAT + cb * 32 + tx] = ((const float*)sh)[tx];
}

// ===== k_B2: combine halves; reorth; Q[j]; new wf; nrm partials; alpha =====
__global__ void k_B2(int j, int last) {
    __shared__ float sh_c[ORDER];
    __shared__ float shn[4];
    int tx = threadIdx.x, lane = tx & 31, w = tx >> 5;

    {   // reduce c-partials (512 row-blocks x 16)
        int k = tx >> 4, i = tx & 15;
        float c = 0.f;
        #pragma unroll 8
        for (int m = 0; m < ROW_BLOCKS / 16; m++)
            c += g_cpart[(m * 16 + i) * 16 + k];
        #pragma unroll
        for (int o = 8; o; o >>= 1) c += __shfl_xor_sync(0xffffffffu, c, o);
        if (i == 0) sh_c[k] = c;
    }
    __syncthreads();

    if (blockIdx.x == 0 && tx == 0) g_alpha[j] = -sh_c[j];
    float invb = 1.0f / fmaxf(g_b[j], 1e-30f);
    int col = blockIdx.x * 128 + tx;

    if (last) {
        if (tx < 128) g_Q[(size_t)j * D_FEAT + col] = g_wf[col] * invb;
        return;
    }

    float nrm = 0.f;
    if (tx < 128) {
        float u = g_upart[col] + g_upart[D_FEAT + col];
        float qv = g_wf[col] * invb;
        g_Q[(size_t)j * D_FEAT + col] = qv;
        float wv = -u;
        for (int k = 0; k < j; k++)
            wv = fmaf(sh_c[k], g_Q[(size_t)k * D_FEAT + col], wv);
        wv = fmaf(sh_c[j], qv, wv);
        g_wf[col] = wv;
        nrm = wv * wv;
    }
    #pragma unroll
    for (int o = 16; o; o >>= 1) nrm += __shfl_xor_sync(0xffffffffu, nrm, o);
    if (lane == 0 && w < 4) shn[w] = nrm;
    __syncthreads();
    if (tx == 0) g_nrm2_part[blockIdx.x] = shn[0] + shn[1] + shn[2] + shn[3];
}

// == k_final: expm (inlined, warp0) + dtheta[p] = D[p].dir / (||D[p]||^2+REG) ==
__global__ void k_final(const float* __restrict__ Dm, float* __restrict__ out) {
    __shared__ float sh_a[8], sh_d[8];
    __shared__ float coeffs[ORDER];
    int p = blockIdx.x;
    int tx = threadIdx.x, lane = tx & 31, w = tx >> 5;

    if (w == 0) {  // exp(-T*DTAU) e0 via lane-parallel double Taylor
        double a = 0.0, bl = 0.0, bu = 0.0;
        if (lane < ORDER) a = (double)g_alpha[lane];
        if (lane >= 1 && lane < ORDER) bl = (double)g_b[lane];
        if (lane < ORDER - 1) bu = (double)g_b[lane + 1];
        double v = (lane == 0) ? 1.0 : 0.0, y = v;
        for (int k = 1; k <= 40; k++) {
            double vp = __shfl_up_sync(0xffffffffu, v, 1);
            double vn = __shfl_down_sync(0xffffffffu, v, 1);
            double t = a * v + bl * vp + bu * vn;
            v = t * (-DTAU / (double)k);
            y += v;
        }
        if (lane < ORDER) coeffs[lane] = (float)((double)g_b[0] * y);
    }
    __syncthreads();

    float cf[ORDER];
    #pragma unroll
    for (int l = 0; l < ORDER; l++) cf[l] = coeffs[l];
    const float* Dp = Dm + (size_t)p * D_FEAT;
    float acc = 0.f, den = 0.f;
    for (int d = tx; d < D_FEAT; d += NW) {
        float dir = 0.f;
        #pragma unroll
        for (int l = 0; l < ORDER; l++) dir = fmaf(cf[l], g_Q[(size_t)l * D_FEAT + d], dir);
        float dv = Dp[d];
        acc = fmaf(dv, dir, acc);
        den = fmaf(dv, dv, den);
    }
    #pragma unroll
    for (int o = 16; o; o >>= 1) {
        acc += __shfl_xor_sync(0xffffffffu, acc, o);
        den += __shfl_xor_sync(0xffffffffu, den, o);
    }
    if (lane == 0) { sh_a[w] = acc; sh_d[w] = den; }
    __syncthreads();
    if (tx == 0) {
        float A = 0.f, Dd = 0.f;
        #pragma unroll
        for (int i = 0; i < 8; i++) { A += sh_a[i]; Dd += sh_d[i]; }
        out[p] = A / (Dd + REG);
    }
}

// --------------------------------- launcher ----------------------------------
extern "C" void kernel_launch(void* const* d_in, const int* in_sizes, int n_in,
                              void* d_out, int out_size) {
    (void)out_size;
    const float* f = nullptr;
    const float* R = nullptr;
    const float* Dm = nullptr;
    for (int i = 0; i < n_in; i++) {
        if (in_sizes[i] == D_FEAT)               f  = (const float*)d_in[i];
        else if (in_sizes[i] == T_RES * D_FEAT)  R  = (const float*)d_in[i];
        else if (in_sizes[i] == ORDER * D_FEAT)  Dm = (const float*)d_in[i];
    }

    k_row_f<<<256, NW>>>(R, f);
    k_prologue_col<<<COL_BLOCKS, NWC>>>(R, f);
    for (int j = 0; j < ORDER; j++) {
        k_A<<<ROW_BLOCKS, NW>>>(R, j, (j == 0) ? COL_BLOCKS : 64);
        if (j < ORDER - 1) k_B1<<<UB1, NWC>>>(R, j);
        k_B2<<<64, NW>>>(j, (j == ORDER - 1) ? 1 : 0);
    }
    k_final<<<ORDER, NW>>>(Dm, (float*)d_out);
}

// round 13
// speedup vs baseline: 1.1159x; 1.1159x over previous
#include <cuda_runtime.h>
#include <math.h>

#define D_FEAT 8192
#define T_RES  2048
#define ORDER  16
#define DTAU   0.08
#define REG    0.0001f
#define EPS_C  1e-15f

#define ROW_BLOCKS 512   // k_A: 4 rows/block, 2 warps per row
#define COL_BLOCKS 256   // prologue col: 32 cols/block, 512 threads
#define UB1       512    // k_B1 blocks: 2 t-halves x 256 col-blocks
#define NW  256
#define NWC 512

// ---------------- device scratch (no allocations allowed) ----------------
__device__ float g_s[ORDER * T_RES];          // s_j = R q_j
__device__ float g_sf[T_RES];                 // R f
__device__ float g_Q[ORDER * D_FEAT];         // Lanczos basis
__device__ float g_wf[D_FEAT];                // current unnormalized basis vector
__device__ float g_upart[2 * D_FEAT];         // t-half partials of u = R^T s_j
__device__ float g_nrm2_part[COL_BLOCKS];     // ||wf||^2 partials
__device__ float g_cpart[ROW_BLOCKS * ORDER]; // per-row-block partials of c_k
__device__ float g_b[ORDER + 1];              // g_b[0]=||F||, g_b[j]=beta[j-1]
__device__ float g_alpha[ORDER];

// R loads: non-coherent with L2 evict_last access policy so the 64MB R matrix
// stays L2-resident across the 33 full sweeps (L2 = 126MB). sm_103a requires
// the cache_hint (createpolicy) form for v4.f32.
__device__ __forceinline__ unsigned long long mk_pol() {
    unsigned long long p;
    asm("createpolicy.fractional.L2::evict_last.b64 %0, 1.0;" : "=l"(p));
    return p;
}
__device__ __forceinline__ float4 ldR(const float4* p, unsigned long long pol) {
    float4 v;
    asm volatile("ld.global.nc.L2::cache_hint.v4.f32 {%0,%1,%2,%3}, [%4], %5;"
                 : "=f"(v.x), "=f"(v.y), "=f"(v.z), "=f"(v.w)
                 : "l"(p), "l"(pol));
    return v;
}

__device__ __forceinline__ void fma4(float4& a, const float4 r, const float4 v) {
    a.x = fmaf(r.x, v.x, a.x); a.y = fmaf(r.y, v.y, a.y);
    a.z = fmaf(r.z, v.z, a.z); a.w = fmaf(r.w, v.w, a.w);
}
__device__ __forceinline__ void fmas(float4& a, const float4 r, const float s) {
    a.x = fmaf(r.x, s, a.x); a.y = fmaf(r.y, s, a.y);
    a.z = fmaf(r.z, s, a.z); a.w = fmaf(r.w, s, a.w);
}

// ================= prologue row: sf = R f (warp per row) =================
__global__ void k_row_f(const float* __restrict__ R, const float* __restrict__ f) {
    int tx = threadIdx.x, lane = tx & 31, w = tx >> 5;
    unsigned long long pol = mk_pol();
    int r = blockIdx.x * 8 + w;
    const float4* R4 = (const float4*)(R + (size_t)r * D_FEAT);
    const float4* f4 = (const float4*)f;
    float4 aA = make_float4(0.f,0.f,0.f,0.f), aB = aA;
    #pragma unroll 8
    for (int it = 0; it < 64; it += 2) {
        int i0 = it * 32 + lane, i1 = i0 + 32;
        fma4(aA, ldR(R4 + i0, pol), f4[i0]);
        fma4(aB, ldR(R4 + i1, pol), f4[i1]);
    }
    float acc = (aA.x + aA.y) + (aA.z + aA.w) + (aB.x + aB.y) + (aB.z + aB.w);
    #pragma unroll
    for (int o = 16; o; o >>= 1) acc += __shfl_xor_sync(0xffffffffu, acc, o);
    if (lane == 0) g_sf[r] = acc;
}

// ====== prologue col: F = R^T sf + E f ; wf = F ; ||F||^2 partials ======
__global__ void k_prologue_col(const float* __restrict__ R, const float* __restrict__ f) {
    __shared__ float s_sm[T_RES];
    __shared__ float4 sh[NWC];
    __shared__ float sh_r1[16], sh_r2[16];
    __shared__ float shE;
    int tx = threadIdx.x, lane = tx & 31, w = tx >> 5;
    unsigned long long pol = mk_pol();
    const float4* f4 = (const float4*)f;

    float ssf = 0.f;
    for (int i = tx; i < T_RES / 4; i += NWC) {
        float4 v = ((const float4*)g_sf)[i];
        ((float4*)s_sm)[i] = v;
        ssf = fmaf(v.x, v.x, fmaf(v.y, v.y, fmaf(v.z, v.z, fmaf(v.w, v.w, ssf))));
    }
    float ff = 0.f;
    for (int i = tx; i < D_FEAT / 4; i += NWC) {
        float4 v = f4[i];
        ff = fmaf(v.x, v.x, fmaf(v.y, v.y, fmaf(v.z, v.z, fmaf(v.w, v.w, ff))));
    }
    #pragma unroll
    for (int o = 16; o; o >>= 1) {
        ssf += __shfl_xor_sync(0xffffffffu, ssf, o);
        ff  += __shfl_xor_sync(0xffffffffu, ff, o);
    }
    if (lane == 0) { sh_r1[w] = ssf; sh_r2[w] = ff; }
    __syncthreads();
    if (tx == 0) {
        float a = 0.f, b = 0.f;
        #pragma unroll
        for (int i = 0; i < 16; i++) { a += sh_r1[i]; b += sh_r2[i]; }
        shE = -a / (b + EPS_C);
    }
    __syncthreads();

    int g = tx & 7, s = tx >> 3;          // s in [0,64)
    const float4* R4 = (const float4*)R;
    size_t cbase = (size_t)blockIdx.x * 8 + g;
    float4 a0 = make_float4(0.f,0.f,0.f,0.f), a1 = a0, a2 = a0, a3 = a0;
    #pragma unroll
    for (int it = 0; it < 32; it += 4) {
        int t0 = (it+0)*64 + s, t1 = (it+1)*64 + s, t2 = (it+2)*64 + s, t3 = (it+3)*64 + s;
        fmas(a0, ldR(R4 + (size_t)t0 * (D_FEAT/4) + cbase, pol), s_sm[t0]);
        fmas(a1, ldR(R4 + (size_t)t1 * (D_FEAT/4) + cbase, pol), s_sm[t1]);
        fmas(a2, ldR(R4 + (size_t)t2 * (D_FEAT/4) + cbase, pol), s_sm[t2]);
        fmas(a3, ldR(R4 + (size_t)t3 * (D_FEAT/4) + cbase, pol), s_sm[t3]);
    }
    a0.x += a1.x; a0.y += a1.y; a0.z += a1.z; a0.w += a1.w;
    a2.x += a3.x; a2.y += a3.y; a2.z += a3.z; a2.w += a3.w;
    a0.x += a2.x; a0.y += a2.y; a0.z += a2.z; a0.w += a2.w;
    sh[tx] = a0;
    #pragma unroll
    for (int off = 256; off >= 8; off >>= 1) {
        __syncthreads();
        if (tx < off) {
            float4 a = sh[tx], b2 = sh[tx + off];
            a.x += b2.x; a.y += b2.y; a.z += b2.z; a.w += b2.w;
            sh[tx] = a;
        }
    }
    __syncthreads();

    if (tx < 32) {
        float u = ((const float*)sh)[tx];
        int col = blockIdx.x * 32 + tx;
        float F = fmaf(shE, f[col], u);
        g_wf[col] = F;
        float nrm = F * F;
        #pragma unroll
        for (int o = 16; o; o >>= 1) nrm += __shfl_xor_sync(0xffffffffu, nrm, o);
        if (tx == 0) g_nrm2_part[blockIdx.x] = nrm;
    }
}

// == k_A: b=||wf||; s_j = R*(wf/b); c-partials (4 rows/block, 2 warps/row) ==
__global__ void k_A(const float* __restrict__ R, int j, int npart) {
    __shared__ float sh_r[8];
    __shared__ float sh_invb;
    __shared__ float shp[8];
    int tx = threadIdx.x, lane = tx & 31, w = tx >> 5;
    unsigned long long pol = mk_pol();

    float p = (tx < npart) ? g_nrm2_part[tx] : 0.f;
    #pragma unroll
    for (int o = 16; o; o >>= 1) p += __shfl_xor_sync(0xffffffffu, p, o);
    if (lane == 0) sh_r[w] = p;
    __syncthreads();
    if (tx == 0) {
        float n = 0.f;
        #pragma unroll
        for (int i = 0; i < 8; i++) n += sh_r[i];
        float b = sqrtf(n);
        if (blockIdx.x == 0) g_b[j] = b;
        sh_invb = 1.0f / fmaxf(b, 1e-30f);
    }
    __syncthreads();

    int r0 = blockIdx.x * 4;
    int row = r0 + (w >> 1), half = w & 1;
    const float4* R4 = (const float4*)(R + (size_t)row * D_FEAT) + half * 1024;
    const float4* w4 = (const float4*)g_wf + half * 1024;
    float4 aA = make_float4(0.f,0.f,0.f,0.f), aB = aA;
    #pragma unroll 8
    for (int it = 0; it < 32; it += 2) {
        int i0 = it * 32 + lane, i1 = i0 + 32;
        fma4(aA, ldR(R4 + i0, pol), w4[i0]);
        fma4(aB, ldR(R4 + i1, pol), w4[i1]);
    }
    float acc = (aA.x + aA.y) + (aA.z + aA.w) + (aB.x + aB.y) + (aB.z + aB.w);
    #pragma unroll
    for (int o = 16; o; o >>= 1) acc += __shfl_xor_sync(0xffffffffu, acc, o);
    if (lane == 0) shp[w] = acc;
    __syncthreads();

    if (w == 0) {
        float d = (lane < 8) ? shp[lane] : 0.f;
        d += __shfl_xor_sync(0xffffffffu, d, 1);   // lanes 0,2,4,6: full row dots
        float invb = sh_invb;
        float s0 = __shfl_sync(0xffffffffu, d, 0) * invb;
        float s1 = __shfl_sync(0xffffffffu, d, 2) * invb;
        float s2 = __shfl_sync(0xffffffffu, d, 4) * invb;
        float s3 = __shfl_sync(0xffffffffu, d, 6) * invb;
        if (lane < 4) {
            float sv = (lane == 0) ? s0 : (lane == 1) ? s1 : (lane == 2) ? s2 : s3;
            g_s[j * T_RES + r0 + lane] = sv;
        }
        if (lane < 16) {
            float cp = 0.f;
            if (lane <= j) {
                if (lane == j) {
                    cp = s0 * s0 + s1 * s1 + s2 * s2 + s3 * s3;
                } else {
                    const float* sk = g_s + (size_t)lane * T_RES + r0;
                    cp = sk[0] * s0 + sk[1] * s1 + sk[2] * s2 + sk[3] * s3;
                }
            }
            g_cpart[blockIdx.x * 16 + lane] = cp;
        }
    }
}

// ===== k_B1: u-half partials: g_upart[th][col] = sum_{t in half} R[t][col]*s_j[t] =====
__global__ void k_B1(const float* __restrict__ R, int j) {
    __shared__ float s_sm[1024];
    __shared__ float4 sh[NWC];
    int tx = threadIdx.x;
    unsigned long long pol = mk_pol();
    int th = blockIdx.x >> 8;       // t-half
    int cb = blockIdx.x & 255;      // column block

    const float4* sj4 = (const float4*)(g_s + (size_t)j * T_RES + th * 1024);
    for (int i = tx; i < 256; i += NWC) ((float4*)s_sm)[i] = sj4[i];
    __syncthreads();

    int g = tx & 7, s = tx >> 3;    // s in [0,64)
    const float4* R4 = (const float4*)R + (size_t)th * 1024 * (D_FEAT / 4);
    size_t cbase = (size_t)cb * 8 + g;
    float4 a0 = make_float4(0.f,0.f,0.f,0.f), a1 = a0, a2 = a0, a3 = a0;
    #pragma unroll
    for (int it = 0; it < 16; it += 4) {
        int t0 = (it+0)*64 + s, t1 = (it+1)*64 + s, t2 = (it+2)*64 + s, t3 = (it+3)*64 + s;
        fmas(a0, ldR(R4 + (size_t)t0 * (D_FEAT/4) + cbase, pol), s_sm[t0]);
        fmas(a1, ldR(R4 + (size_t)t1 * (D_FEAT/4) + cbase, pol), s_sm[t1]);
        fmas(a2, ldR(R4 + (size_t)t2 * (D_FEAT/4) + cbase, pol), s_sm[t2]);
        fmas(a3, ldR(R4 + (size_t)t3 * (D_FEAT/4) + cbase, pol), s_sm[t3]);
    }
    a0.x += a1.x; a0.y += a1.y; a0.z += a1.z; a0.w += a1.w;
    a2.x += a3.x; a2.y += a3.y; a2.z += a3.z; a2.w += a3.w;
    a0.x += a2.x; a0.y += a2.y; a0.z += a2.z; a0.w += a2.w;
    sh[tx] = a0;
    #pragma unroll
    for (int off = 256; off >= 8; off >>= 1) {
        __syncthreads();
        if (tx < off) {
            float4 a = sh[tx], b2 = sh[tx + off];
            a.x += b2.x; a.y += b2.y; a.z += b2.z; a.w += b2.w;
            sh[tx] = a;
        }
    }
    __syncthreads();
    if (tx < 32) g_upart[th * D_FEAT + cb * 32 + tx] = ((const float*)sh)[tx];
}

// ===== k_B2: combine halves; reorth; Q[j]; new wf; nrm partials; alpha =====
__global__ void k_B2(int j, int last) {
    __shared__ float sh_c[ORDER];
    __shared__ float shn[4];
    int tx = threadIdx.x, lane = tx & 31, w = tx >> 5;

    {   // reduce c-partials (512 row-blocks x 16)
        int k = tx >> 4, i = tx & 15;
        float c = 0.f;
        #pragma unroll 8
        for (int m = 0; m < ROW_BLOCKS / 16; m++)
            c += g_cpart[(m * 16 + i) * 16 + k];
        #pragma unroll
        for (int o = 8; o; o >>= 1) c += __shfl_xor_sync(0xffffffffu, c, o);
        if (i == 0) sh_c[k] = c;
    }
    __syncthreads();

    if (blockIdx.x == 0 && tx == 0) g_alpha[j] = -sh_c[j];
    float invb = 1.0f / fmaxf(g_b[j], 1e-30f);
    int col = blockIdx.x * 128 + tx;

    if (last) {
        if (tx < 128) g_Q[(size_t)j * D_FEAT + col] = g_wf[col] * invb;
        return;
    }

    float nrm = 0.f;
    if (tx < 128) {
        float u = g_upart[col] + g_upart[D_FEAT + col];
        float qv = g_wf[col] * invb;
        g_Q[(size_t)j * D_FEAT + col] = qv;
        float wv = -u;
        for (int k = 0; k < j; k++)
            wv = fmaf(sh_c[k], g_Q[(size_t)k * D_FEAT + col], wv);
        wv = fmaf(sh_c[j], qv, wv);
        g_wf[col] = wv;
        nrm = wv * wv;
    }
    #pragma unroll
    for (int o = 16; o; o >>= 1) nrm += __shfl_xor_sync(0xffffffffu, nrm, o);
    if (lane == 0 && w < 4) shn[w] = nrm;
    __syncthreads();
    if (tx == 0) g_nrm2_part[blockIdx.x] = shn[0] + shn[1] + shn[2] + shn[3];
}

// == k_final: expm (inlined, warp0) + dtheta[p] = D[p].dir / (||D[p]||^2+REG) ==
__global__ void k_final(const float* __restrict__ Dm, float* __restrict__ out) {
    __shared__ float sh_a[8], sh_d[8];
    __shared__ float coeffs[ORDER];
    int p = blockIdx.x;
    int tx = threadIdx.x, lane = tx & 31, w = tx >> 5;

    if (w == 0) {  // exp(-T*DTAU) e0 via lane-parallel double Taylor
        double a = 0.0, bl = 0.0, bu = 0.0;
        if (lane < ORDER) a = (double)g_alpha[lane];
        if (lane >= 1 && lane < ORDER) bl = (double)g_b[lane];
        if (lane < ORDER - 1) bu = (double)g_b[lane + 1];
        double v = (lane == 0) ? 1.0 : 0.0, y = v;
        for (int k = 1; k <= 40; k++) {
            double vp = __shfl_up_sync(0xffffffffu, v, 1);
            double vn = __shfl_down_sync(0xffffffffu, v, 1);
            double t = a * v + bl * vp + bu * vn;
            v = t * (-DTAU / (double)k);
            y += v;
        }
        if (lane < ORDER) coeffs[lane] = (float)((double)g_b[0] * y);
    }
    __syncthreads();

    float cf[ORDER];
    #pragma unroll
    for (int l = 0; l < ORDER; l++) cf[l] = coeffs[l];
    const float* Dp = Dm + (size_t)p * D_FEAT;
    float acc = 0.f, den = 0.f;
    for (int d = tx; d < D_FEAT; d += NW) {
        float dir = 0.f;
        #pragma unroll
        for (int l = 0; l < ORDER; l++) dir = fmaf(cf[l], g_Q[(size_t)l * D_FEAT + d], dir);
        float dv = Dp[d];
        acc = fmaf(dv, dir, acc);
        den = fmaf(dv, dv, den);
    }
    #pragma unroll
    for (int o = 16; o; o >>= 1) {
        acc += __shfl_xor_sync(0xffffffffu, acc, o);
        den += __shfl_xor_sync(0xffffffffu, den, o);
    }
    if (lane == 0) { sh_a[w] = acc; sh_d[w] = den; }
    __syncthreads();
    if (tx == 0) {
        float A = 0.f, Dd = 0.f;
        #pragma unroll
        for (int i = 0; i < 8; i++) { A += sh_a[i]; Dd += sh_d[i]; }
        out[p] = A / (Dd + REG);
    }
}

// --------------------------------- launcher ----------------------------------
extern "C" void kernel_launch(void* const* d_in, const int* in_sizes, int n_in,
                              void* d_out, int out_size) {
    (void)out_size;
    const float* f = nullptr;
    const float* R = nullptr;
    const float* Dm = nullptr;
    for (int i = 0; i < n_in; i++) {
        if (in_sizes[i] == D_FEAT)               f  = (const float*)d_in[i];
        else if (in_sizes[i] == T_RES * D_FEAT)  R  = (const float*)d_in[i];
        else if (in_sizes[i] == ORDER * D_FEAT)  Dm = (const float*)d_in[i];
    }

    k_row_f<<<256, NW>>>(R, f);
    k_prologue_col<<<COL_BLOCKS, NWC>>>(R, f);
    for (int j = 0; j < ORDER; j++) {
        k_A<<<ROW_BLOCKS, NW>>>(R, j, (j == 0) ? COL_BLOCKS : 64);
        if (j < ORDER - 1) k_B1<<<UB1, NWC>>>(R, j);
        k_B2<<<64, NW>>>(j, (j == ORDER - 1) ? 1 : 0);
    }
    k_final<<<ORDER, NW>>>(Dm, (float*)d_out);
}